// round 9
// baseline (speedup 1.0000x reference)
#include <cuda_runtime.h>

// 3-layer LSTM (IN=5, H=50) + FC(50->1), B=1024, T=512.
// v8: v7's balanced layer-pipeline with WARP-PURE groups (576 threads).
//   L1 (tid 0-99,   warps 0-3):  layer1 @ t = ph   (2-way K-split, pair shfl)
//   Sp (tid 100-127, warp 3 tail): x(ph+1) prefetch
//   L2 (tid 128-327, warps 4-10): layer2 @ t = ph-1 (4-way K-split, quad shfl)
//   L3 (tid 352-551, warps 11-17): layer3 @ t = ph-2
// No warp contains two gate groups -> no serialized divergent phase bodies
// (v7's regression). One __syncthreads per phase; v vectors double-buffered
// on parity. No dynamic register indexing anywhere. Cell states in registers.

#define T_STEPS   512
#define IN_DIM    5
#define HID       50
#define NB        7
#define NTHREADS  576
#define GRID      148
#define WSTR      808          // floats per kq block (200 rows * 4 + 8 pad)

// smem offsets (floats)
enum {
    W1_OFF = 0,                 // 14 * 808 = 11312
    W2_OFF = 11312,             // 25 * 808 = 20200
    W3_OFF = 31512,             // 20200
    V1_OFF = 51712,             // 2 bufs * 7 * 60   [x(5),pad,h1(50),pad4]
    V2_OFF = 52552,             // 2 bufs * 7 * 108  [h1(50),h2(50),pad8]
    V3_OFF = 54064,             // 2 bufs * 7 * 108  [h2(50),h3(50),pad8]
    SH_FLOATS = 55576           // 222304 bytes
};
#define V1S 60
#define V2S 108
#define V1B (NB * V1S)          // 420
#define V2B (NB * V2S)          // 756

typedef unsigned long long ull;

__device__ __forceinline__ ull ffma2(ull a, ull b, ull c) {
    ull d;
    asm("fma.rn.f32x2 %0, %1, %2, %3;" : "=l"(d) : "l"(a), "l"(b), "l"(c));
    return d;
}
__device__ __forceinline__ float fast_ex2(float x) {
    float y; asm("ex2.approx.ftz.f32 %0, %1;" : "=f"(y) : "f"(x)); return y;
}
__device__ __forceinline__ float fast_rcp(float x) {
    float y; asm("rcp.approx.ftz.f32 %0, %1;" : "=f"(y) : "f"(x)); return y;
}
__device__ __forceinline__ float sigm(float x) {
    return fast_rcp(1.0f + fast_ex2(-1.4426950408889634f * x));
}
__device__ __forceinline__ float tanh_acc(float x) {
    float r = fast_rcp(1.0f + fast_ex2(-2.8853900817779268f * x));
    return r + r - 1.0f;
}
__device__ __forceinline__ float lohi(ull a) {
    float lo, hi;
    asm("mov.b64 {%0, %1}, %2;" : "=f"(lo), "=f"(hi) : "l"(a));
    return lo + hi;
}
__device__ __forceinline__ float pick4(float a0, float a1, float a2, float a3,
                                       int k) {
    float x = (k & 1) ? a1 : a0;
    float y = (k & 1) ? a3 : a2;
    return (k & 2) ? y : x;
}

// ---- Layer 1: 100 threads, 2-way K-split over 14 kq blocks ----
__device__ __forceinline__ void layer1_phase(float* sh, int p, int q, int j,
                                             int ks, unsigned pmask,
                                             const float bz[4], float c1[4]) {
    ull acc[4][NB];
#pragma unroll
    for (int g = 0; g < 4; g++)
#pragma unroll
        for (int b = 0; b < NB; b++) acc[g][b] = 0ull;

    const float* vb = sh + V1_OFF + p * V1B;
#pragma unroll
    for (int i = 0; i < 7; i++) {
        const int kq0 = 2 * i;   // + ks at runtime
        const ulonglong2* wq = reinterpret_cast<const ulonglong2*>(
            sh + W1_OFF + (ks + kq0) * WSTR);
        ulonglong2 w0 = wq[j];
        ulonglong2 w1 = wq[j + HID];
        ulonglong2 w2 = wq[j + 2 * HID];
        ulonglong2 w3 = wq[j + 3 * HID];
#pragma unroll
        for (int b = 0; b < NB; b++) {
            ulonglong2 v = *reinterpret_cast<const ulonglong2*>(
                vb + b * V1S + (ks + kq0) * 4);
            acc[0][b] = ffma2(w0.x, v.x, acc[0][b]);
            acc[0][b] = ffma2(w0.y, v.y, acc[0][b]);
            acc[1][b] = ffma2(w1.x, v.x, acc[1][b]);
            acc[1][b] = ffma2(w1.y, v.y, acc[1][b]);
            acc[2][b] = ffma2(w2.x, v.x, acc[2][b]);
            acc[2][b] = ffma2(w2.y, v.y, acc[2][b]);
            acc[3][b] = ffma2(w3.x, v.x, acc[3][b]);
            acc[3][b] = ffma2(w3.y, v.y, acc[3][b]);
        }
    }
    float s[4][NB];
#pragma unroll
    for (int g = 0; g < 4; g++)
#pragma unroll
        for (int b = 0; b < NB; b++) {
            float v = lohi(acc[g][b]);
            v += __shfl_xor_sync(pmask, v, 1);
            s[g][b] = v;
        }
    // ks=0 updates batches 0-3 (c1[0..3]); ks=1 updates 4-6 (c1[0..2])
    if (ks == 0) {
#pragma unroll
        for (int b = 0; b < 4; b++) {
            float iv = sigm(s[0][b] + bz[0]);
            float fv = sigm(s[1][b] + bz[1]);
            float gv = tanh_acc(s[2][b] + bz[2]);
            float ov = sigm(s[3][b] + bz[3]);
            c1[b] = fv * c1[b] + iv * gv;
            float h = ov * tanh_acc(c1[b]);
            sh[V1_OFF + q * V1B + b * V1S + 6 + j] = h;
            sh[V2_OFF + q * V2B + b * V2S + j]     = h;
        }
    } else {
#pragma unroll
        for (int b = 0; b < 3; b++) {
            const int bb = b + 4;
            float iv = sigm(s[0][bb] + bz[0]);
            float fv = sigm(s[1][bb] + bz[1]);
            float gv = tanh_acc(s[2][bb] + bz[2]);
            float ov = sigm(s[3][bb] + bz[3]);
            c1[b] = fv * c1[b] + iv * gv;
            float h = ov * tanh_acc(c1[b]);
            sh[V1_OFF + q * V1B + bb * V1S + 6 + j] = h;
            sh[V2_OFF + q * V2B + bb * V2S + j]     = h;
        }
    }
}

// ---- Layers 2/3: 200 threads, 4-way K-split over KQ=25 ----
template<bool HAS2>
__device__ __forceinline__ void layer_hid_phase(float* sh,
                                                const float* __restrict__ shw,
                                                const float* __restrict__ vrd,
                                                int j, int ks, unsigned qmask,
                                                const float bz[4],
                                                float& ca, float& cb,
                                                int wr1, int wr2) {
    ull acc[4][NB];
#pragma unroll
    for (int g = 0; g < 4; g++)
#pragma unroll
        for (int b = 0; b < NB; b++) acc[g][b] = 0ull;

#pragma unroll
    for (int i = 0; i < 6; i++) {
        const int kq0 = 4 * i;
        const ulonglong2* wq = reinterpret_cast<const ulonglong2*>(
            shw + (ks + kq0) * WSTR);
        ulonglong2 w0 = wq[j];
        ulonglong2 w1 = wq[j + HID];
        ulonglong2 w2 = wq[j + 2 * HID];
        ulonglong2 w3 = wq[j + 3 * HID];
#pragma unroll
        for (int b = 0; b < NB; b++) {
            ulonglong2 v = *reinterpret_cast<const ulonglong2*>(
                vrd + b * V2S + (ks + kq0) * 4);
            acc[0][b] = ffma2(w0.x, v.x, acc[0][b]);
            acc[0][b] = ffma2(w0.y, v.y, acc[0][b]);
            acc[1][b] = ffma2(w1.x, v.x, acc[1][b]);
            acc[1][b] = ffma2(w1.y, v.y, acc[1][b]);
            acc[2][b] = ffma2(w2.x, v.x, acc[2][b]);
            acc[2][b] = ffma2(w2.y, v.y, acc[2][b]);
            acc[3][b] = ffma2(w3.x, v.x, acc[3][b]);
            acc[3][b] = ffma2(w3.y, v.y, acc[3][b]);
        }
    }
    if (ks == 0) {   // tail kq = 24
        const ulonglong2* wq = reinterpret_cast<const ulonglong2*>(
            shw + 24 * WSTR);
        ulonglong2 w0 = wq[j];
        ulonglong2 w1 = wq[j + HID];
        ulonglong2 w2 = wq[j + 2 * HID];
        ulonglong2 w3 = wq[j + 3 * HID];
#pragma unroll
        for (int b = 0; b < NB; b++) {
            ulonglong2 v = *reinterpret_cast<const ulonglong2*>(
                vrd + b * V2S + 24 * 4);
            acc[0][b] = ffma2(w0.x, v.x, acc[0][b]);
            acc[0][b] = ffma2(w0.y, v.y, acc[0][b]);
            acc[1][b] = ffma2(w1.x, v.x, acc[1][b]);
            acc[1][b] = ffma2(w1.y, v.y, acc[1][b]);
            acc[2][b] = ffma2(w2.x, v.x, acc[2][b]);
            acc[2][b] = ffma2(w2.y, v.y, acc[2][b]);
            acc[3][b] = ffma2(w3.x, v.x, acc[3][b]);
            acc[3][b] = ffma2(w3.y, v.y, acc[3][b]);
        }
    }

    float s[4][NB];
#pragma unroll
    for (int g = 0; g < 4; g++)
#pragma unroll
        for (int b = 0; b < NB; b++) {
            float v = lohi(acc[g][b]);
            v += __shfl_xor_sync(qmask, v, 1);
            v += __shfl_xor_sync(qmask, v, 2);
            s[g][b] = v;
        }

    float t0[4], t1[4];
#pragma unroll
    for (int g = 0; g < 4; g++) {
        t0[g] = pick4(s[g][0], s[g][2], s[g][4], s[g][6], ks) + bz[g];
        t1[g] = pick4(s[g][1], s[g][3], s[g][5], s[g][5], ks) + bz[g];
    }
    const int b0 = 2 * ks;
    {
        float iv = sigm(t0[0]);
        float fv = sigm(t0[1]);
        float gv = tanh_acc(t0[2]);
        float ov = sigm(t0[3]);
        ca = fv * ca + iv * gv;
        float h = ov * tanh_acc(ca);
        sh[wr1 + b0 * V2S] = h;
        if (HAS2) sh[wr2 + b0 * V2S] = h;
    }
    if (ks < 3) {
        const int b1 = 2 * ks + 1;
        float iv = sigm(t1[0]);
        float fv = sigm(t1[1]);
        float gv = tanh_acc(t1[2]);
        float ov = sigm(t1[3]);
        cb = fv * cb + iv * gv;
        float h = ov * tanh_acc(cb);
        sh[wr1 + b1 * V2S] = h;
        if (HAS2) sh[wr2 + b1 * V2S] = h;
    }
}

__global__ void __launch_bounds__(NTHREADS, 1)
lstm3_pipe_kernel(const float* __restrict__ x,
                  const float* __restrict__ Wih1, const float* __restrict__ Whh1,
                  const float* __restrict__ bih1, const float* __restrict__ bhh1,
                  const float* __restrict__ Wih2, const float* __restrict__ Whh2,
                  const float* __restrict__ bih2, const float* __restrict__ bhh2,
                  const float* __restrict__ Wih3, const float* __restrict__ Whh3,
                  const float* __restrict__ bih3, const float* __restrict__ bhh3,
                  const float* __restrict__ fcW, const float* __restrict__ fcb,
                  float* __restrict__ out) {
    extern __shared__ float sh[];
    const int tid = threadIdx.x;
    const int bid = blockIdx.x;
    const int lane = tid & 31;

    int b0, cnt;
    if (bid < 136) { b0 = bid * 7;               cnt = 7; }
    else           { b0 = 952 + (bid - 136) * 6; cnt = 6; }

    // zero v buffers
    for (int i = V1_OFF + tid; i < SH_FLOATS; i += NTHREADS) sh[i] = 0.0f;

    // stage weights: [kq][row][k&3], kq-stride WSTR
    for (int idx = tid; idx < 200 * 56; idx += NTHREADS) {
        int g = idx / 56, k = idx - g * 56;
        float v;
        if (k < IN_DIM)       v = Wih1[g * IN_DIM + k];
        else if (k == IN_DIM) v = 0.0f;
        else                  v = Whh1[g * HID + (k - 6)];
        sh[W1_OFF + (k >> 2) * WSTR + g * 4 + (k & 3)] = v;
    }
    for (int idx = tid; idx < 200 * 100; idx += NTHREADS) {
        int g = idx / 100, k = idx - g * 100;
        float v = (k < HID) ? Wih2[g * HID + k] : Whh2[g * HID + (k - HID)];
        sh[W2_OFF + (k >> 2) * WSTR + g * 4 + (k & 3)] = v;
    }
    for (int idx = tid; idx < 200 * 100; idx += NTHREADS) {
        int g = idx / 100, k = idx - g * 100;
        float v = (k < HID) ? Wih3[g * HID + k] : Whh3[g * HID + (k - HID)];
        sh[W3_OFF + (k >> 2) * WSTR + g * 4 + (k & 3)] = v;
    }
    // x(t=0) into v1 buf0
    if (tid < NB * IN_DIM) {
        int b = tid / IN_DIM, d = tid - b * IN_DIM;
        if (b < cnt)
            sh[V1_OFF + b * V1S + d] = x[(size_t)(b0 + b) * T_STEPS * IN_DIM + d];
    }

    // ---- warp-pure group assignment ----
    const bool isL1 = (tid < 100);                    // warps 0-3 (partial)
    const bool isSp = (tid >= 100 && tid < 128);      // warp 3 tail: prefetch
    const bool isL2 = (tid >= 128 && tid < 328);      // warps 4-10 (partial)
    const bool isL3 = (tid >= 352 && tid < 552);      // warps 11-17 (partial)

    int j = 0, ks = 0;
    if (isL1)      { j = tid >> 1;       ks = tid & 1; }
    else if (isL2) { int i2 = tid - 128; j = i2 >> 2; ks = i2 & 3; }
    else if (isL3) { int i3 = tid - 352; j = i3 >> 2; ks = i3 & 3; }

    const unsigned pmask = 0x3u << (lane & ~1);   // L1 pair mask
    const unsigned qmask = 0xFu << (lane & ~3);   // L2/L3 quad mask

    float bz[4] = {0.f, 0.f, 0.f, 0.f};
    if (isL1) {
#pragma unroll
        for (int g = 0; g < 4; g++)
            bz[g] = bih1[g * HID + j] + bhh1[g * HID + j];
    } else if (isL2) {
#pragma unroll
        for (int g = 0; g < 4; g++)
            bz[g] = bih2[g * HID + j] + bhh2[g * HID + j];
    } else if (isL3) {
#pragma unroll
        for (int g = 0; g < 4; g++)
            bz[g] = bih3[g * HID + j] + bhh3[g * HID + j];
    }

    float c1[4] = {0.f, 0.f, 0.f, 0.f};   // L1: 4 (ks=0) or 3 (ks=1) batches
    float ca = 0.f, cb = 0.f;             // L2/L3 cell states

    const int sp_i = tid - 100;           // 28 spares x 2 slots = 56 >= 35
    __syncthreads();

    for (int ph = 0; ph < T_STEPS + 2; ph++) {
        const int p = ph & 1, q = p ^ 1;

        if (isL1) {
            if (ph < T_STEPS)
                layer1_phase(sh, p, q, j, ks, pmask, bz, c1);
        } else if (isL2) {
            if (ph >= 1 && ph <= T_STEPS)
                layer_hid_phase<true>(sh, sh + W2_OFF,
                                      sh + V2_OFF + p * V2B,
                                      j, ks, qmask, bz, ca, cb,
                                      V2_OFF + q * V2B + HID + j,
                                      V3_OFF + q * V2B + j);
        } else if (isL3) {
            if (ph >= 2)
                layer_hid_phase<false>(sh, sh + W3_OFF,
                                       sh + V3_OFF + p * V2B,
                                       j, ks, qmask, bz, ca, cb,
                                       V3_OFF + q * V2B + HID + j, 0);
        } else if (isSp) {
            if (ph + 1 < T_STEPS) {
#pragma unroll
                for (int r = 0; r < 2; r++) {
                    int s0 = sp_i + 28 * r;
                    if (s0 < NB * IN_DIM) {
                        int bb = s0 / IN_DIM, dd = s0 - bb * IN_DIM;
                        if (bb < cnt)
                            sh[V1_OFF + q * V1B + bb * V1S + dd] =
                                x[(size_t)(b0 + bb) * T_STEPS * IN_DIM
                                  + (ph + 1) * IN_DIM + dd];
                    }
                }
            }
        }
        __syncthreads();
    }

    // FC: final h3 in v3 buf0
    if (tid < cnt) {
        float a = fcb[0];
#pragma unroll
        for (int jj = 0; jj < HID; jj++)
            a += fcW[jj] * sh[V3_OFF + tid * V2S + HID + jj];
        out[b0 + tid] = a;
    }
}

extern "C" void kernel_launch(void* const* d_in, const int* in_sizes, int n_in,
                              void* d_out, int out_size) {
    const float* x    = (const float*)d_in[0];
    const float* Wih1 = (const float*)d_in[1];
    const float* Whh1 = (const float*)d_in[2];
    const float* bih1 = (const float*)d_in[3];
    const float* bhh1 = (const float*)d_in[4];
    const float* Wih2 = (const float*)d_in[5];
    const float* Whh2 = (const float*)d_in[6];
    const float* bih2 = (const float*)d_in[7];
    const float* bhh2 = (const float*)d_in[8];
    const float* Wih3 = (const float*)d_in[9];
    const float* Whh3 = (const float*)d_in[10];
    const float* bih3 = (const float*)d_in[11];
    const float* bhh3 = (const float*)d_in[12];
    const float* fcW  = (const float*)d_in[13];
    const float* fcb  = (const float*)d_in[14];

    size_t shbytes = (size_t)SH_FLOATS * sizeof(float);
    cudaFuncSetAttribute(lstm3_pipe_kernel,
                         cudaFuncAttributeMaxDynamicSharedMemorySize,
                         (int)shbytes);
    lstm3_pipe_kernel<<<GRID, NTHREADS, shbytes>>>(
        x, Wih1, Whh1, bih1, bhh1, Wih2, Whh2, bih2, bhh2,
        Wih3, Whh3, bih3, bhh3, fcW, fcb, (float*)d_out);
}

// round 10
// speedup vs baseline: 1.3874x; 1.3874x over previous
#include <cuda_runtime.h>

// 3-layer LSTM (IN=5, H=50) + FC(50->1), B=1024, T=512.
// v9: layer-pipelined, warp-pure, balanced, SMALL-ACC (batch-packed f32x2).
//   L1 (tid 0-99,   warps 0-3):   layer1 @ t=ph   (2-way K-split, 28 k/lane)
//   Sp (tid 100-127, warp 3 tail): x(ph+1) prefetch
//   L2 (tid 128-327, warps 4-10): layer2 @ t=ph-1 (4-way K-split, 25 k/lane)
//   L3 (tid 352-551, warps 11-17): layer3 @ t=ph-2
// f32x2 lanes = BATCH pairs -> acc[4][4] ull = 32 regs (v8's 56-reg acc
// spilled under the 576-thread cap). Weights [k][j*4+g]; vectors transposed
// [k][batch(8)] so v loads are 2 broadcast LDS.128 per k. One barrier/phase.

#define T_STEPS   512
#define IN_DIM    5
#define HID       50
#define NB        7
#define NTHREADS  576
#define GRID      148
#define W1ROW     208          // 200 + 8  (2-lane k-split conflict-free)
#define W2ROW     200          // 200 + 0  (4-lane k-split conflict-free)

// smem offsets (floats)
enum {
    W1_OFF = 0,                 // 56 rows * 208 = 11648
    W2_OFF = 11648,             // 100 * 200 = 20000
    W3_OFF = 31648,             // 20000
    V1_OFF = 51648,             // 2 bufs * 56 rows * 8 = 896  [x(0-4),pad5,h1(6-55)]
    V2_OFF = 52544,             // 2 bufs * 100 * 8 = 1600     [h1(0-49),h2(50-99)]
    V3_OFF = 54144,             // 1600                        [h2,h3]
    SH_FLOATS = 55744           // 222976 bytes
};
#define V1B 448
#define V2B 800

typedef unsigned long long ull;

__device__ __forceinline__ ull ffma2(ull a, ull b, ull c) {
    ull d;
    asm("fma.rn.f32x2 %0, %1, %2, %3;" : "=l"(d) : "l"(a), "l"(b), "l"(c));
    return d;
}
__device__ __forceinline__ ull add2(ull a, ull b) {
    ull d;
    asm("add.rn.f32x2 %0, %1, %2;" : "=l"(d) : "l"(a), "l"(b));
    return d;
}
__device__ __forceinline__ ull pack2(float w) {
    ull d;
    asm("mov.b64 %0, {%1, %1};" : "=l"(d) : "f"(w));
    return d;
}
__device__ __forceinline__ void unpk(ull a, float& lo, float& hi) {
    asm("mov.b64 {%0, %1}, %2;" : "=f"(lo), "=f"(hi) : "l"(a));
}
__device__ __forceinline__ float fast_ex2(float x) {
    float y; asm("ex2.approx.ftz.f32 %0, %1;" : "=f"(y) : "f"(x)); return y;
}
__device__ __forceinline__ float fast_rcp(float x) {
    float y; asm("rcp.approx.ftz.f32 %0, %1;" : "=f"(y) : "f"(x)); return y;
}
__device__ __forceinline__ float sigm(float x) {
    return fast_rcp(1.0f + fast_ex2(-1.4426950408889634f * x));
}
__device__ __forceinline__ float tanh_acc(float x) {
    float r = fast_rcp(1.0f + fast_ex2(-2.8853900817779268f * x));
    return r + r - 1.0f;
}

// Accumulate 4 gates x 4 batch-pairs over k = ks + STRIDE*i, i < NK.
template<int NK, int STRIDE, int WROW>
__device__ __forceinline__ void accum(const float* __restrict__ shw,
                                      const float* __restrict__ vrd,
                                      int j, int ks, ull acc[4][4]) {
#pragma unroll
    for (int g = 0; g < 4; g++)
#pragma unroll
        for (int bp = 0; bp < 4; bp++) acc[g][bp] = 0ull;

#pragma unroll
    for (int i = 0; i < NK; i++) {
        const int k = ks + STRIDE * i;
        const float4 w = *reinterpret_cast<const float4*>(shw + k * WROW + 4 * j);
        const ulonglong2 va = *reinterpret_cast<const ulonglong2*>(vrd + k * 8);
        const ulonglong2 vb = *reinterpret_cast<const ulonglong2*>(vrd + k * 8 + 4);
        ull w0 = pack2(w.x), w1 = pack2(w.y), w2 = pack2(w.z), w3 = pack2(w.w);
        acc[0][0] = ffma2(w0, va.x, acc[0][0]);
        acc[0][1] = ffma2(w0, va.y, acc[0][1]);
        acc[0][2] = ffma2(w0, vb.x, acc[0][2]);
        acc[0][3] = ffma2(w0, vb.y, acc[0][3]);
        acc[1][0] = ffma2(w1, va.x, acc[1][0]);
        acc[1][1] = ffma2(w1, va.y, acc[1][1]);
        acc[1][2] = ffma2(w1, vb.x, acc[1][2]);
        acc[1][3] = ffma2(w1, vb.y, acc[1][3]);
        acc[2][0] = ffma2(w2, va.x, acc[2][0]);
        acc[2][1] = ffma2(w2, va.y, acc[2][1]);
        acc[2][2] = ffma2(w2, vb.x, acc[2][2]);
        acc[2][3] = ffma2(w2, vb.y, acc[2][3]);
        acc[3][0] = ffma2(w3, va.x, acc[3][0]);
        acc[3][1] = ffma2(w3, va.y, acc[3][1]);
        acc[3][2] = ffma2(w3, vb.x, acc[3][2]);
        acc[3][3] = ffma2(w3, vb.y, acc[3][3]);
    }
}

// ---- L2/L3 phase: 4-way K-split, 2-round payload-halving ull butterfly ----
template<bool HAS2>
__device__ __forceinline__ void layer_hid_phase(float* sh,
                                                const float* __restrict__ shw,
                                                const float* __restrict__ vrd,
                                                int j, int ks, unsigned qmask,
                                                const float bz[4],
                                                float& ca, float& cb,
                                                int wr1, int wr2) {
    ull acc[4][4];
    accum<25, 4, W2ROW>(shw, vrd, j, ks, acc);

    const bool k1 = (ks & 2) != 0;
    const bool k0 = (ks & 1) != 0;
    float ta[4], tb[4];
#pragma unroll
    for (int g = 0; g < 4; g++) {
        ull s0 = k1 ? acc[g][0] : acc[g][2];
        ull s1 = k1 ? acc[g][1] : acc[g][3];
        ull K0 = k1 ? acc[g][2] : acc[g][0];
        ull K1 = k1 ? acc[g][3] : acc[g][1];
        ull m0 = add2(K0, __shfl_xor_sync(qmask, s0, 2));
        ull m1 = add2(K1, __shfl_xor_sync(qmask, s1, 2));
        ull s  = k0 ? m0 : m1;
        ull K  = k0 ? m1 : m0;
        ull tot = add2(K, __shfl_xor_sync(qmask, s, 1));
        float lo, hi; unpk(tot, lo, hi);
        ta[g] = lo + bz[g];
        tb[g] = hi + bz[g];
    }
    // batches 2ks (ta) and 2ks+1 (tb)
    float ha, hb;
    {
        float iv = sigm(ta[0]), fv = sigm(ta[1]);
        float gv = tanh_acc(ta[2]), ov = sigm(ta[3]);
        ca = fv * ca + iv * gv;
        ha = ov * tanh_acc(ca);
    }
    {
        float iv = sigm(tb[0]), fv = sigm(tb[1]);
        float gv = tanh_acc(tb[2]), ov = sigm(tb[3]);
        cb = fv * cb + iv * gv;
        hb = ov * tanh_acc(cb);
    }
    float2 hh = make_float2(ha, hb);
    *reinterpret_cast<float2*>(sh + wr1 + 2 * ks) = hh;
    if (HAS2) *reinterpret_cast<float2*>(sh + wr2 + 2 * ks) = hh;
}

// ---- L1 phase: 2-way K-split, 1-round butterfly, 4 batches/thread ----
__device__ __forceinline__ void layer1_phase(float* sh, int p, int q, int j,
                                             int ks, unsigned pmask,
                                             const float bz[4], float c1[4]) {
    ull acc[4][4];
    accum<28, 2, W1ROW>(sh + W1_OFF, sh + V1_OFF + p * V1B, j, ks, acc);

    const bool kb = (ks != 0);
    float t0[4], t1[4], t2[4], t3[4];
#pragma unroll
    for (int g = 0; g < 4; g++) {
        ull s0 = kb ? acc[g][0] : acc[g][2];
        ull s1 = kb ? acc[g][1] : acc[g][3];
        ull K0 = kb ? acc[g][2] : acc[g][0];
        ull K1 = kb ? acc[g][3] : acc[g][1];
        ull m0 = add2(K0, __shfl_xor_sync(pmask, s0, 1));  // bp 2ks
        ull m1 = add2(K1, __shfl_xor_sync(pmask, s1, 1));  // bp 2ks+1
        float a, b; unpk(m0, a, b);
        t0[g] = a + bz[g]; t1[g] = b + bz[g];
        unpk(m1, a, b);
        t2[g] = a + bz[g]; t3[g] = b + bz[g];
    }
    // batches 4ks .. 4ks+3
    float h0, h1v, h2v, h3v;
    {
        float iv = sigm(t0[0]), fv = sigm(t0[1]);
        float gv = tanh_acc(t0[2]), ov = sigm(t0[3]);
        c1[0] = fv * c1[0] + iv * gv; h0 = ov * tanh_acc(c1[0]);
    }
    {
        float iv = sigm(t1[0]), fv = sigm(t1[1]);
        float gv = tanh_acc(t1[2]), ov = sigm(t1[3]);
        c1[1] = fv * c1[1] + iv * gv; h1v = ov * tanh_acc(c1[1]);
    }
    {
        float iv = sigm(t2[0]), fv = sigm(t2[1]);
        float gv = tanh_acc(t2[2]), ov = sigm(t2[3]);
        c1[2] = fv * c1[2] + iv * gv; h2v = ov * tanh_acc(c1[2]);
    }
    {
        float iv = sigm(t3[0]), fv = sigm(t3[1]);
        float gv = tanh_acc(t3[2]), ov = sigm(t3[3]);
        c1[3] = fv * c1[3] + iv * gv; h3v = ov * tanh_acc(c1[3]);
    }
    float4 hq = make_float4(h0, h1v, h2v, h3v);
    *reinterpret_cast<float4*>(sh + V1_OFF + q * V1B + (6 + j) * 8 + 4 * ks) = hq;
    *reinterpret_cast<float4*>(sh + V2_OFF + q * V2B + j * 8 + 4 * ks)       = hq;
}

__global__ void __launch_bounds__(NTHREADS, 1)
lstm3_pipe_kernel(const float* __restrict__ x,
                  const float* __restrict__ Wih1, const float* __restrict__ Whh1,
                  const float* __restrict__ bih1, const float* __restrict__ bhh1,
                  const float* __restrict__ Wih2, const float* __restrict__ Whh2,
                  const float* __restrict__ bih2, const float* __restrict__ bhh2,
                  const float* __restrict__ Wih3, const float* __restrict__ Whh3,
                  const float* __restrict__ bih3, const float* __restrict__ bhh3,
                  const float* __restrict__ fcW, const float* __restrict__ fcb,
                  float* __restrict__ out) {
    extern __shared__ float sh[];
    const int tid = threadIdx.x;
    const int bid = blockIdx.x;
    const int lane = tid & 31;

    int b0, cnt;
    if (bid < 136) { b0 = bid * 7;               cnt = 7; }
    else           { b0 = 952 + (bid - 136) * 6; cnt = 6; }

    // zero v buffers (both parities, incl. pad columns/rows)
    for (int i = V1_OFF + tid; i < SH_FLOATS; i += NTHREADS) sh[i] = 0.0f;

    // stage W1: [k][j*4+g], row k: k<5 = Wih1, k=5 pad0, k>=6 = Whh1
    for (int idx = tid; idx < 200 * 56; idx += NTHREADS) {
        int gr = idx / 56, k = idx - gr * 56;       // gr = g*50 + j
        int g = gr / 50, j = gr - g * 50;
        float v;
        if (k < IN_DIM)       v = Wih1[gr * IN_DIM + k];
        else if (k == IN_DIM) v = 0.0f;
        else                  v = Whh1[gr * HID + (k - 6)];
        sh[W1_OFF + k * W1ROW + j * 4 + g] = v;
    }
    // stage W2/W3: [k][j*4+g], k<50 = Wih, k>=50 = Whh
    for (int idx = tid; idx < 200 * 100; idx += NTHREADS) {
        int gr = idx / 100, k = idx - gr * 100;
        int g = gr / 50, j = gr - g * 50;
        float v = (k < HID) ? Wih2[gr * HID + k] : Whh2[gr * HID + (k - HID)];
        sh[W2_OFF + k * W2ROW + j * 4 + g] = v;
    }
    for (int idx = tid; idx < 200 * 100; idx += NTHREADS) {
        int gr = idx / 100, k = idx - gr * 100;
        int g = gr / 50, j = gr - g * 50;
        float v = (k < HID) ? Wih3[gr * HID + k] : Whh3[gr * HID + (k - HID)];
        sh[W3_OFF + k * W2ROW + j * 4 + g] = v;
    }
    // x(t=0) into v1 buf0 rows 0-4, column b
    if (tid < NB * IN_DIM) {
        int b = tid / IN_DIM, d = tid - b * IN_DIM;
        if (b < cnt)
            sh[V1_OFF + d * 8 + b] = x[(size_t)(b0 + b) * T_STEPS * IN_DIM + d];
    }

    // ---- warp-pure groups (as v8) ----
    const bool isL1 = (tid < 100);
    const bool isSp = (tid >= 100 && tid < 128);
    const bool isL2 = (tid >= 128 && tid < 328);
    const bool isL3 = (tid >= 352 && tid < 552);

    int j = 0, ks = 0;
    if (isL1)      { j = tid >> 1;       ks = tid & 1; }
    else if (isL2) { int i2 = tid - 128; j = i2 >> 2; ks = i2 & 3; }
    else if (isL3) { int i3 = tid - 352; j = i3 >> 2; ks = i3 & 3; }

    const unsigned pmask = 0x3u << (lane & ~1);
    const unsigned qmask = 0xFu << (lane & ~3);

    float bz[4] = {0.f, 0.f, 0.f, 0.f};
    if (isL1) {
#pragma unroll
        for (int g = 0; g < 4; g++)
            bz[g] = bih1[g * HID + j] + bhh1[g * HID + j];
    } else if (isL2) {
#pragma unroll
        for (int g = 0; g < 4; g++)
            bz[g] = bih2[g * HID + j] + bhh2[g * HID + j];
    } else if (isL3) {
#pragma unroll
        for (int g = 0; g < 4; g++)
            bz[g] = bih3[g * HID + j] + bhh3[g * HID + j];
    }

    float c1[4] = {0.f, 0.f, 0.f, 0.f};
    float ca = 0.f, cb = 0.f;

    const int sp_i = tid - 100;
    __syncthreads();

    for (int ph = 0; ph < T_STEPS + 2; ph++) {
        const int p = ph & 1, q = p ^ 1;

        if (isL1) {
            if (ph < T_STEPS)
                layer1_phase(sh, p, q, j, ks, pmask, bz, c1);
        } else if (isL2) {
            if (ph >= 1 && ph <= T_STEPS)
                layer_hid_phase<true>(sh, sh + W2_OFF,
                                      sh + V2_OFF + p * V2B,
                                      j, ks, qmask, bz, ca, cb,
                                      V2_OFF + q * V2B + (50 + j) * 8,
                                      V3_OFF + q * V2B + j * 8);
        } else if (isL3) {
            if (ph >= 2)
                layer_hid_phase<false>(sh, sh + W3_OFF,
                                       sh + V3_OFF + p * V2B,
                                       j, ks, qmask, bz, ca, cb,
                                       V3_OFF + q * V2B + (50 + j) * 8, 0);
        } else if (isSp) {
            if (ph + 1 < T_STEPS) {
#pragma unroll
                for (int r = 0; r < 2; r++) {
                    int s0 = sp_i + 28 * r;
                    if (s0 < NB * IN_DIM) {
                        int bb = s0 / IN_DIM, dd = s0 - bb * IN_DIM;
                        if (bb < cnt)
                            sh[V1_OFF + q * V1B + dd * 8 + bb] =
                                x[(size_t)(b0 + bb) * T_STEPS * IN_DIM
                                  + (ph + 1) * IN_DIM + dd];
                    }
                }
            }
        }
        __syncthreads();
    }

    // FC: h3(511) written at ph=513 -> buf q=0; row 50+j, column b
    if (tid < cnt) {
        float a = fcb[0];
#pragma unroll
        for (int jj = 0; jj < HID; jj++)
            a += fcW[jj] * sh[V3_OFF + (50 + jj) * 8 + tid];
        out[b0 + tid] = a;
    }
}

extern "C" void kernel_launch(void* const* d_in, const int* in_sizes, int n_in,
                              void* d_out, int out_size) {
    const float* x    = (const float*)d_in[0];
    const float* Wih1 = (const float*)d_in[1];
    const float* Whh1 = (const float*)d_in[2];
    const float* bih1 = (const float*)d_in[3];
    const float* bhh1 = (const float*)d_in[4];
    const float* Wih2 = (const float*)d_in[5];
    const float* Whh2 = (const float*)d_in[6];
    const float* bih2 = (const float*)d_in[7];
    const float* bhh2 = (const float*)d_in[8];
    const float* Wih3 = (const float*)d_in[9];
    const float* Whh3 = (const float*)d_in[10];
    const float* bih3 = (const float*)d_in[11];
    const float* bhh3 = (const float*)d_in[12];
    const float* fcW  = (const float*)d_in[13];
    const float* fcb  = (const float*)d_in[14];

    size_t shbytes = (size_t)SH_FLOATS * sizeof(float);
    cudaFuncSetAttribute(lstm3_pipe_kernel,
                         cudaFuncAttributeMaxDynamicSharedMemorySize,
                         (int)shbytes);
    lstm3_pipe_kernel<<<GRID, NTHREADS, shbytes>>>(
        x, Wih1, Whh1, bih1, bhh1, Wih2, Whh2, bih2, bhh2,
        Wih3, Whh3, bih3, bhh3, fcW, fcb, (float*)d_out);
}

// round 11
// speedup vs baseline: 1.3902x; 1.0021x over previous
#include <cuda_runtime.h>

// 3-layer LSTM (IN=5, H=50) + FC(50->1), B=1024, T=512.
// v10 = v9 (layer-pipelined, warp-pure, batch-packed f32x2 accs) with the
// block-wide barrier replaced by PAIRWISE NAMED BARRIERS:
//   bar1 (id 1, 352 thr): G1 (warps 0-3: L1 + x-prefetch) <-> G2 (warps 4-10: L2)
//   bar2 (id 2, 448 thr): G2 <-> G3 (warps 11-17: L3)
// G2 syncs bar1 then bar2 each phase. G1 and G3 never rendezvous directly:
// G3@ph is gated by G1@ph-1 (one phase of slack) -> stall jitter in one
// group no longer serializes the whole block, and post-barrier LDS bursts
// de-synchronize. Data/WAR hazards all ordered by the owning pairwise bar.

#define T_STEPS   512
#define IN_DIM    5
#define HID       50
#define NB        7
#define NTHREADS  576
#define GRID      148
#define W1ROW     208
#define W2ROW     200

// smem offsets (floats)
enum {
    W1_OFF = 0,                 // 56 rows * 208 = 11648
    W2_OFF = 11648,             // 100 * 200 = 20000
    W3_OFF = 31648,             // 20000
    V1_OFF = 51648,             // 2 bufs * 56 rows * 8  [x(0-4),pad5,h1(6-55)]
    V2_OFF = 52544,             // 2 bufs * 100 * 8      [h1,h2]
    V3_OFF = 54144,             // 1600                  [h2,h3]
    SH_FLOATS = 55744           // 222976 bytes
};
#define V1B 448
#define V2B 800

typedef unsigned long long ull;

__device__ __forceinline__ ull ffma2(ull a, ull b, ull c) {
    ull d;
    asm("fma.rn.f32x2 %0, %1, %2, %3;" : "=l"(d) : "l"(a), "l"(b), "l"(c));
    return d;
}
__device__ __forceinline__ ull add2(ull a, ull b) {
    ull d;
    asm("add.rn.f32x2 %0, %1, %2;" : "=l"(d) : "l"(a), "l"(b));
    return d;
}
__device__ __forceinline__ ull pack2(float w) {
    ull d;
    asm("mov.b64 %0, {%1, %1};" : "=l"(d) : "f"(w));
    return d;
}
__device__ __forceinline__ void unpk(ull a, float& lo, float& hi) {
    asm("mov.b64 {%0, %1}, %2;" : "=f"(lo), "=f"(hi) : "l"(a));
}
__device__ __forceinline__ float fast_ex2(float x) {
    float y; asm("ex2.approx.ftz.f32 %0, %1;" : "=f"(y) : "f"(x)); return y;
}
__device__ __forceinline__ float fast_rcp(float x) {
    float y; asm("rcp.approx.ftz.f32 %0, %1;" : "=f"(y) : "f"(x)); return y;
}
__device__ __forceinline__ float sigm(float x) {
    return fast_rcp(1.0f + fast_ex2(-1.4426950408889634f * x));
}
__device__ __forceinline__ float tanh_acc(float x) {
    float r = fast_rcp(1.0f + fast_ex2(-2.8853900817779268f * x));
    return r + r - 1.0f;
}

// Accumulate 4 gates x 4 batch-pairs over k = ks + STRIDE*i, i < NK.
template<int NK, int STRIDE, int WROW>
__device__ __forceinline__ void accum(const float* __restrict__ shw,
                                      const float* __restrict__ vrd,
                                      int j, int ks, ull acc[4][4]) {
#pragma unroll
    for (int g = 0; g < 4; g++)
#pragma unroll
        for (int bp = 0; bp < 4; bp++) acc[g][bp] = 0ull;

#pragma unroll
    for (int i = 0; i < NK; i++) {
        const int k = ks + STRIDE * i;
        const float4 w = *reinterpret_cast<const float4*>(shw + k * WROW + 4 * j);
        const ulonglong2 va = *reinterpret_cast<const ulonglong2*>(vrd + k * 8);
        const ulonglong2 vb = *reinterpret_cast<const ulonglong2*>(vrd + k * 8 + 4);
        ull w0 = pack2(w.x), w1 = pack2(w.y), w2 = pack2(w.z), w3 = pack2(w.w);
        acc[0][0] = ffma2(w0, va.x, acc[0][0]);
        acc[0][1] = ffma2(w0, va.y, acc[0][1]);
        acc[0][2] = ffma2(w0, vb.x, acc[0][2]);
        acc[0][3] = ffma2(w0, vb.y, acc[0][3]);
        acc[1][0] = ffma2(w1, va.x, acc[1][0]);
        acc[1][1] = ffma2(w1, va.y, acc[1][1]);
        acc[1][2] = ffma2(w1, vb.x, acc[1][2]);
        acc[1][3] = ffma2(w1, vb.y, acc[1][3]);
        acc[2][0] = ffma2(w2, va.x, acc[2][0]);
        acc[2][1] = ffma2(w2, va.y, acc[2][1]);
        acc[2][2] = ffma2(w2, vb.x, acc[2][2]);
        acc[2][3] = ffma2(w2, vb.y, acc[2][3]);
        acc[3][0] = ffma2(w3, va.x, acc[3][0]);
        acc[3][1] = ffma2(w3, va.y, acc[3][1]);
        acc[3][2] = ffma2(w3, vb.x, acc[3][2]);
        acc[3][3] = ffma2(w3, vb.y, acc[3][3]);
    }
}

// ---- L2/L3 phase: 4-way K-split, payload-halving ull butterfly ----
template<bool HAS2>
__device__ __forceinline__ void layer_hid_phase(float* sh,
                                                const float* __restrict__ shw,
                                                const float* __restrict__ vrd,
                                                int j, int ks, unsigned qmask,
                                                const float bz[4],
                                                float& ca, float& cb,
                                                int wr1, int wr2) {
    ull acc[4][4];
    accum<25, 4, W2ROW>(shw, vrd, j, ks, acc);

    const bool k1 = (ks & 2) != 0;
    const bool k0 = (ks & 1) != 0;
    float ta[4], tb[4];
#pragma unroll
    for (int g = 0; g < 4; g++) {
        ull s0 = k1 ? acc[g][0] : acc[g][2];
        ull s1 = k1 ? acc[g][1] : acc[g][3];
        ull K0 = k1 ? acc[g][2] : acc[g][0];
        ull K1 = k1 ? acc[g][3] : acc[g][1];
        ull m0 = add2(K0, __shfl_xor_sync(qmask, s0, 2));
        ull m1 = add2(K1, __shfl_xor_sync(qmask, s1, 2));
        ull s  = k0 ? m0 : m1;
        ull K  = k0 ? m1 : m0;
        ull tot = add2(K, __shfl_xor_sync(qmask, s, 1));
        float lo, hi; unpk(tot, lo, hi);
        ta[g] = lo + bz[g];
        tb[g] = hi + bz[g];
    }
    float ha, hb;
    {
        float iv = sigm(ta[0]), fv = sigm(ta[1]);
        float gv = tanh_acc(ta[2]), ov = sigm(ta[3]);
        ca = fv * ca + iv * gv;
        ha = ov * tanh_acc(ca);
    }
    {
        float iv = sigm(tb[0]), fv = sigm(tb[1]);
        float gv = tanh_acc(tb[2]), ov = sigm(tb[3]);
        cb = fv * cb + iv * gv;
        hb = ov * tanh_acc(cb);
    }
    float2 hh = make_float2(ha, hb);
    *reinterpret_cast<float2*>(sh + wr1 + 2 * ks) = hh;
    if (HAS2) *reinterpret_cast<float2*>(sh + wr2 + 2 * ks) = hh;
}

// ---- L1 phase: 2-way K-split, 1-round butterfly, 4 batches/thread ----
__device__ __forceinline__ void layer1_phase(float* sh, int p, int q, int j,
                                             int ks, unsigned pmask,
                                             const float bz[4], float c1[4]) {
    ull acc[4][4];
    accum<28, 2, W1ROW>(sh + W1_OFF, sh + V1_OFF + p * V1B, j, ks, acc);

    const bool kb = (ks != 0);
    float t0[4], t1[4], t2[4], t3[4];
#pragma unroll
    for (int g = 0; g < 4; g++) {
        ull s0 = kb ? acc[g][0] : acc[g][2];
        ull s1 = kb ? acc[g][1] : acc[g][3];
        ull K0 = kb ? acc[g][2] : acc[g][0];
        ull K1 = kb ? acc[g][3] : acc[g][1];
        ull m0 = add2(K0, __shfl_xor_sync(pmask, s0, 1));
        ull m1 = add2(K1, __shfl_xor_sync(pmask, s1, 1));
        float a, b; unpk(m0, a, b);
        t0[g] = a + bz[g]; t1[g] = b + bz[g];
        unpk(m1, a, b);
        t2[g] = a + bz[g]; t3[g] = b + bz[g];
    }
    float h0, h1v, h2v, h3v;
    {
        float iv = sigm(t0[0]), fv = sigm(t0[1]);
        float gv = tanh_acc(t0[2]), ov = sigm(t0[3]);
        c1[0] = fv * c1[0] + iv * gv; h0 = ov * tanh_acc(c1[0]);
    }
    {
        float iv = sigm(t1[0]), fv = sigm(t1[1]);
        float gv = tanh_acc(t1[2]), ov = sigm(t1[3]);
        c1[1] = fv * c1[1] + iv * gv; h1v = ov * tanh_acc(c1[1]);
    }
    {
        float iv = sigm(t2[0]), fv = sigm(t2[1]);
        float gv = tanh_acc(t2[2]), ov = sigm(t2[3]);
        c1[2] = fv * c1[2] + iv * gv; h2v = ov * tanh_acc(c1[2]);
    }
    {
        float iv = sigm(t3[0]), fv = sigm(t3[1]);
        float gv = tanh_acc(t3[2]), ov = sigm(t3[3]);
        c1[3] = fv * c1[3] + iv * gv; h3v = ov * tanh_acc(c1[3]);
    }
    float4 hq = make_float4(h0, h1v, h2v, h3v);
    *reinterpret_cast<float4*>(sh + V1_OFF + q * V1B + (6 + j) * 8 + 4 * ks) = hq;
    *reinterpret_cast<float4*>(sh + V2_OFF + q * V2B + j * 8 + 4 * ks)       = hq;
}

__global__ void __launch_bounds__(NTHREADS, 1)
lstm3_pipe_kernel(const float* __restrict__ x,
                  const float* __restrict__ Wih1, const float* __restrict__ Whh1,
                  const float* __restrict__ bih1, const float* __restrict__ bhh1,
                  const float* __restrict__ Wih2, const float* __restrict__ Whh2,
                  const float* __restrict__ bih2, const float* __restrict__ bhh2,
                  const float* __restrict__ Wih3, const float* __restrict__ Whh3,
                  const float* __restrict__ bih3, const float* __restrict__ bhh3,
                  const float* __restrict__ fcW, const float* __restrict__ fcb,
                  float* __restrict__ out) {
    extern __shared__ float sh[];
    const int tid = threadIdx.x;
    const int bid = blockIdx.x;
    const int lane = tid & 31;
    const int wid = tid >> 5;

    int b0, cnt;
    if (bid < 136) { b0 = bid * 7;               cnt = 7; }
    else           { b0 = 952 + (bid - 136) * 6; cnt = 6; }

    // zero v buffers
    for (int i = V1_OFF + tid; i < SH_FLOATS; i += NTHREADS) sh[i] = 0.0f;

    // stage W1: [k][j*4+g]
    for (int idx = tid; idx < 200 * 56; idx += NTHREADS) {
        int gr = idx / 56, k = idx - gr * 56;
        int g = gr / 50, j = gr - g * 50;
        float v;
        if (k < IN_DIM)       v = Wih1[gr * IN_DIM + k];
        else if (k == IN_DIM) v = 0.0f;
        else                  v = Whh1[gr * HID + (k - 6)];
        sh[W1_OFF + k * W1ROW + j * 4 + g] = v;
    }
    for (int idx = tid; idx < 200 * 100; idx += NTHREADS) {
        int gr = idx / 100, k = idx - gr * 100;
        int g = gr / 50, j = gr - g * 50;
        float v = (k < HID) ? Wih2[gr * HID + k] : Whh2[gr * HID + (k - HID)];
        sh[W2_OFF + k * W2ROW + j * 4 + g] = v;
    }
    for (int idx = tid; idx < 200 * 100; idx += NTHREADS) {
        int gr = idx / 100, k = idx - gr * 100;
        int g = gr / 50, j = gr - g * 50;
        float v = (k < HID) ? Wih3[gr * HID + k] : Whh3[gr * HID + (k - HID)];
        sh[W3_OFF + k * W2ROW + j * 4 + g] = v;
    }
    // x(t=0)
    if (tid < NB * IN_DIM) {
        int b = tid / IN_DIM, d = tid - b * IN_DIM;
        if (b < cnt)
            sh[V1_OFF + d * 8 + b] = x[(size_t)(b0 + b) * T_STEPS * IN_DIM + d];
    }

    const bool isL1 = (tid < 100);
    const bool isSp = (tid >= 100 && tid < 128);
    const bool isL2 = (tid >= 128 && tid < 328);
    const bool isL3 = (tid >= 352 && tid < 552);

    int j = 0, ks = 0;
    if (isL1)      { j = tid >> 1;       ks = tid & 1; }
    else if (isL2) { int i2 = tid - 128; j = i2 >> 2; ks = i2 & 3; }
    else if (isL3) { int i3 = tid - 352; j = i3 >> 2; ks = i3 & 3; }

    const unsigned pmask = 0x3u << (lane & ~1);
    const unsigned qmask = 0xFu << (lane & ~3);

    float bz[4] = {0.f, 0.f, 0.f, 0.f};
    if (isL1) {
#pragma unroll
        for (int g = 0; g < 4; g++)
            bz[g] = bih1[g * HID + j] + bhh1[g * HID + j];
    } else if (isL2) {
#pragma unroll
        for (int g = 0; g < 4; g++)
            bz[g] = bih2[g * HID + j] + bhh2[g * HID + j];
    } else if (isL3) {
#pragma unroll
        for (int g = 0; g < 4; g++)
            bz[g] = bih3[g * HID + j] + bhh3[g * HID + j];
    }

    float c1[4] = {0.f, 0.f, 0.f, 0.f};
    float ca = 0.f, cb = 0.f;

    const int sp_i = tid - 100;
    __syncthreads();   // weights + v init visible to all

    for (int ph = 0; ph < T_STEPS + 2; ph++) {
        const int p = ph & 1, q = p ^ 1;

        if (wid < 4) {              // G1: L1 + spares
            if (isL1) {
                if (ph < T_STEPS)
                    layer1_phase(sh, p, q, j, ks, pmask, bz, c1);
            } else if (isSp) {
                if (ph + 1 < T_STEPS) {
#pragma unroll
                    for (int r = 0; r < 2; r++) {
                        int s0 = sp_i + 28 * r;
                        if (s0 < NB * IN_DIM) {
                            int bb = s0 / IN_DIM, dd = s0 - bb * IN_DIM;
                            if (bb < cnt)
                                sh[V1_OFF + q * V1B + dd * 8 + bb] =
                                    x[(size_t)(b0 + bb) * T_STEPS * IN_DIM
                                      + (ph + 1) * IN_DIM + dd];
                        }
                    }
                }
            }
            asm volatile("bar.sync 1, 352;" ::: "memory");
        } else if (wid < 11) {      // G2: L2
            if (isL2 && ph >= 1 && ph <= T_STEPS)
                layer_hid_phase<true>(sh, sh + W2_OFF,
                                      sh + V2_OFF + p * V2B,
                                      j, ks, qmask, bz, ca, cb,
                                      V2_OFF + q * V2B + (50 + j) * 8,
                                      V3_OFF + q * V2B + j * 8);
            asm volatile("bar.sync 1, 352;" ::: "memory");
            asm volatile("bar.sync 2, 448;" ::: "memory");
        } else {                    // G3: L3
            if (isL3 && ph >= 2)
                layer_hid_phase<false>(sh, sh + W3_OFF,
                                       sh + V3_OFF + p * V2B,
                                       j, ks, qmask, bz, ca, cb,
                                       V3_OFF + q * V2B + (50 + j) * 8, 0);
            asm volatile("bar.sync 2, 448;" ::: "memory");
        }
    }
    __syncthreads();

    // FC: h3(511) written at ph=513 -> buf q=0; row 50+j, column b
    if (tid < cnt) {
        float a = fcb[0];
#pragma unroll
        for (int jj = 0; jj < HID; jj++)
            a += fcW[jj] * sh[V3_OFF + (50 + jj) * 8 + tid];
        out[b0 + tid] = a;
    }
}

extern "C" void kernel_launch(void* const* d_in, const int* in_sizes, int n_in,
                              void* d_out, int out_size) {
    const float* x    = (const float*)d_in[0];
    const float* Wih1 = (const float*)d_in[1];
    const float* Whh1 = (const float*)d_in[2];
    const float* bih1 = (const float*)d_in[3];
    const float* bhh1 = (const float*)d_in[4];
    const float* Wih2 = (const float*)d_in[5];
    const float* Whh2 = (const float*)d_in[6];
    const float* bih2 = (const float*)d_in[7];
    const float* bhh2 = (const float*)d_in[8];
    const float* Wih3 = (const float*)d_in[9];
    const float* Whh3 = (const float*)d_in[10];
    const float* bih3 = (const float*)d_in[11];
    const float* bhh3 = (const float*)d_in[12];
    const float* fcW  = (const float*)d_in[13];
    const float* fcb  = (const float*)d_in[14];

    size_t shbytes = (size_t)SH_FLOATS * sizeof(float);
    cudaFuncSetAttribute(lstm3_pipe_kernel,
                         cudaFuncAttributeMaxDynamicSharedMemorySize,
                         (int)shbytes);
    lstm3_pipe_kernel<<<GRID, NTHREADS, shbytes>>>(
        x, Wih1, Whh1, bih1, bhh1, Wih2, Whh2, bih2, bhh2,
        Wih3, Whh3, bih3, bhh3, fcW, fcb, (float*)d_out);
}